// round 14
// baseline (speedup 1.0000x reference)
#include <cuda_runtime.h>
#include <cuda_bf16.h>
#include <stdint.h>

// ---------------- problem constants (shapes fixed by the dataset) -----------
#define MAXN 100000
#define MAXE 1600000
#define IN_C 128
#define HID_C 128
#define OUT_C 64
#define SCAN_BT 1024
#define FG_BLOCKS 888          // grid for fused gather+gemm (6 blocks/SM)

// ---------------- device scratch (no allocs; referenced directly) -----------
// g_deg / g_cnt are zero at module load; cleanup_kernel restores them to zero
// every call (off the critical path), keeping kernel_launch deterministic.
__device__ __align__(16) float g_deg [MAXN];
__device__ __align__(16) float g_dinv[MAXN];
__device__ __align__(16) int   g_cnt [MAXN];
__device__ __align__(16) int   g_cur [MAXN];
__device__ __align__(16) int   g_off [MAXN + 1];
__device__ __align__(16) int   g_bsum[128];
__device__ __align__(16) int2  g_csr [MAXE];          // (src, w-as-bits)
__device__ __align__(16) float g_h1[(size_t)MAXN * HID_C];
__device__ __align__(16) float g_h2[(size_t)MAXN * OUT_C];
__device__ __align__(16) float g_z [(size_t)MAXN * OUT_C];

// ---------------- degree + in-edge counting (arrays pre-zeroed) -------------
__global__ void deg_cnt_kernel(const int* __restrict__ dst,
                               const float* __restrict__ ew, int ne) {
    int e = blockIdx.x * blockDim.x + threadIdx.x;
    if (e < ne) {
        int d = dst[e];
        atomicAdd(&g_deg[d], ew[e]);
        atomicAdd(&g_cnt[d], 1);
    }
}

// ---------------- scan pass A: dinv + per-block sums of cnt -----------------
__global__ void scanA_kernel(int n) {
    __shared__ int wsum[32];
    int tid = threadIdx.x;
    int i = blockIdx.x * SCAN_BT + tid;
    int v = 0;
    if (i < n) {
        v = g_cnt[i];
        g_dinv[i] = rsqrtf(g_deg[i] + 1.0f);   // +1 = self-loop weight
    }
    int s = v;
#pragma unroll
    for (int o = 16; o > 0; o >>= 1) s += __shfl_down_sync(0xffffffffu, s, o);
    if ((tid & 31) == 0) wsum[tid >> 5] = s;
    __syncthreads();
    if (tid < 32) {
        int t = wsum[tid];
#pragma unroll
        for (int o = 16; o > 0; o >>= 1) t += __shfl_down_sync(0xffffffffu, t, o);
        if (tid == 0) g_bsum[blockIdx.x] = t;
    }
}

// ---------------- scan pass B: full exclusive scan -> g_off, g_cur ----------
__global__ void scanB_kernel(int n, int nb) {
    __shared__ int bsh[128];
    __shared__ int wpre[32];
    int tid = threadIdx.x;
    int lane = tid & 31;
    int wid = tid >> 5;

    if (tid < 128) bsh[tid] = (tid < nb) ? g_bsum[tid] : 0;
    __syncthreads();
#pragma unroll
    for (int o = 1; o < 128; o <<= 1) {
        int y = 0;
        if (tid >= o && tid < 128) y = bsh[tid - o];
        __syncthreads();
        if (tid >= o && tid < 128) bsh[tid] += y;
        __syncthreads();
    }
    int bpre = bsh[blockIdx.x] - g_bsum[blockIdx.x];   // exclusive block prefix

    int i = blockIdx.x * SCAN_BT + tid;
    int v = (i < n) ? g_cnt[i] : 0;
    int x = v;
#pragma unroll
    for (int o = 1; o < 32; o <<= 1) {
        int y = __shfl_up_sync(0xffffffffu, x, o);
        if (lane >= o) x += y;
    }
    if (lane == 31) wpre[wid] = x;
    __syncthreads();
    if (wid == 0) {
        int t = wpre[lane];
        int tv = t;
#pragma unroll
        for (int o = 1; o < 32; o <<= 1) {
            int y = __shfl_up_sync(0xffffffffu, tv, o);
            if (lane >= o) tv += y;
        }
        wpre[lane] = tv - t;
    }
    __syncthreads();
    int excl = bpre + wpre[wid] + (x - v);
    if (i < n) {
        g_off[i] = excl;
        g_cur[i] = excl;
        if (i == n - 1) g_off[n] = excl + v;
    }
}

// fill CSR: (src, w) pairs grouped by dst
__global__ void fill_kernel(const int* __restrict__ src,
                            const int* __restrict__ dst,
                            const float* __restrict__ ew, int ne) {
    int e = blockIdx.x * blockDim.x + threadIdx.x;
    if (e >= ne) return;
    int s = src[e];
    int d = dst[e];
    int slot = atomicAdd(&g_cur[d], 1);
    float w = g_dinv[s] * ew[e] * g_dinv[d];
    g_csr[slot] = make_int2(s, __float_as_int(w));
}

// restore scratch counters to zero for the next call (determinism)
__global__ void cleanup_kernel(int n) {
    int i = blockIdx.x * blockDim.x + threadIdx.x;
    if (i < n) { g_deg[i] = 0.0f; g_cnt[i] = 0; }
}

// ---------------- tiled FP32 GEMM (layer 1: h1 = x @ W1) --------------------
__global__ void gemm1_kernel(const float* __restrict__ A,
                             const float* __restrict__ W, int nrows) {
    constexpr int NOUT = HID_C;
    constexpr int CPT = NOUT / 16;
    __shared__ float As[64][33];
    __shared__ float Ws[32 * NOUT];

    int tid = threadIdx.x;
    int tx = tid & 15, ty = tid >> 4;
    int row0 = blockIdx.x * 64;

    float acc[4][CPT];
#pragma unroll
    for (int i = 0; i < 4; i++)
#pragma unroll
        for (int j = 0; j < CPT; j++) acc[i][j] = 0.0f;

    for (int k0 = 0; k0 < 128; k0 += 32) {
#pragma unroll
        for (int i = 0; i < 2; i++) {
            int idx = tid + i * 256;
            int r  = idx >> 3;
            int cs = (idx & 7) * 4;
            float4 v = make_float4(0.f, 0.f, 0.f, 0.f);
            int row = row0 + r;
            if (row < nrows) v = *(const float4*)(A + (size_t)row * 128 + k0 + cs);
            As[r][cs + 0] = v.x; As[r][cs + 1] = v.y;
            As[r][cs + 2] = v.z; As[r][cs + 3] = v.w;
        }
        constexpr int WV = (32 * NOUT) / 4 / 256;
        const float4* Wg = (const float4*)(W + k0 * NOUT);
        float4* Wsv = (float4*)Ws;
#pragma unroll
        for (int i = 0; i < WV; i++) Wsv[tid + i * 256] = Wg[tid + i * 256];
        __syncthreads();

#pragma unroll
        for (int k = 0; k < 32; k++) {
            float a0 = As[ty * 4 + 0][k];
            float a1v = As[ty * 4 + 1][k];
            float a2 = As[ty * 4 + 2][k];
            float a3 = As[ty * 4 + 3][k];
            const float* wrow = &Ws[k * NOUT + tx * CPT];
#pragma unroll
            for (int j = 0; j < CPT; j++) {
                float b = wrow[j];
                acc[0][j] += a0 * b;
                acc[1][j] += a1v * b;
                acc[2][j] += a2 * b;
                acc[3][j] += a3 * b;
            }
        }
        __syncthreads();
    }

#pragma unroll
    for (int i = 0; i < 4; i++) {
        int row = row0 + ty * 4 + i;
        if (row < nrows) {
            float* cp = g_h1 + (size_t)row * NOUT + tx * CPT;
#pragma unroll
            for (int j = 0; j < CPT; j += 4)
                *(float4*)(cp + j) = make_float4(acc[i][j], acc[i][j + 1],
                                                 acc[i][j + 2], acc[i][j + 3]);
        }
    }
}

// ---------------- FUSED layer-1 aggregation + layer-2 GEMM -------------------
// Per warp/node: a1 = h1[n]*dinv^2 + sum_e w_e h1[src_e] (in regs, 4/lane)
//               act = relu(a1 + b1); h2[n] = act @ W2  (lane owns 2 cols)
__global__ __launch_bounds__(256) void gather_gemm_kernel(
        const float* __restrict__ W2, const float* __restrict__ b1, int n) {
    __shared__ float Wsm[128 * OUT_C];       // 32 KB

    int tid = threadIdx.x;
    // stage W2 once per block (grid-stride over nodes amortizes this)
    {
        const float4* Wg = (const float4*)W2;
        float4* Ws4 = (float4*)Wsm;
#pragma unroll
        for (int i = 0; i < (128 * OUT_C / 4) / 256; i++)
            Ws4[tid + i * 256] = Wg[tid + i * 256];
    }
    __syncthreads();

    int lane = tid & 31;
    int wstart = blockIdx.x * 8 + (tid >> 5);   // 8 warps per block

    for (int node = wstart; node < n; node += FG_BLOCKS * 8) {
        float di = g_dinv[node];
        float sc = di * di;

        float a0, a1r, a2, a3;
        {
            float4 f = *(const float4*)(g_h1 + (size_t)node * 128 + lane * 4);
            a0 = f.x * sc; a1r = f.y * sc; a2 = f.z * sc; a3 = f.w * sc;
        }

        int i   = g_off[node];
        int end = g_off[node + 1];

        for (; i + 4 <= end; i += 4) {
            int2 c0 = g_csr[i];
            int2 c1 = g_csr[i + 1];
            int2 c2 = g_csr[i + 2];
            int2 c3 = g_csr[i + 3];
            const float* p0 = g_h1 + (size_t)c0.x * 128 + lane * 4;
            const float* p1 = g_h1 + (size_t)c1.x * 128 + lane * 4;
            const float* p2 = g_h1 + (size_t)c2.x * 128 + lane * 4;
            const float* p3 = g_h1 + (size_t)c3.x * 128 + lane * 4;
            float w0 = __int_as_float(c0.y), w1 = __int_as_float(c1.y);
            float w2 = __int_as_float(c2.y), w3 = __int_as_float(c3.y);
            float4 v0 = *(const float4*)p0;
            float4 v1 = *(const float4*)p1;
            float4 v2 = *(const float4*)p2;
            float4 v3 = *(const float4*)p3;
            a0  += v0.x * w0 + v1.x * w1 + v2.x * w2 + v3.x * w3;
            a1r += v0.y * w0 + v1.y * w1 + v2.y * w2 + v3.y * w3;
            a2  += v0.z * w0 + v1.z * w1 + v2.z * w2 + v3.z * w3;
            a3  += v0.w * w0 + v1.w * w1 + v2.w * w2 + v3.w * w3;
        }
        for (; i < end; i++) {
            int2 c = g_csr[i];
            float w = __int_as_float(c.y);
            const float* p = g_h1 + (size_t)c.x * 128 + lane * 4;
            float4 v = *(const float4*)p;
            a0 += v.x * w; a1r += v.y * w; a2 += v.z * w; a3 += v.w * w;
        }

        // bias + relu (activation row distributed: lane holds dims 4l..4l+3)
        {
            float4 b = *(const float4*)(b1 + lane * 4);
            a0  = fmaxf(a0  + b.x, 0.0f);
            a1r = fmaxf(a1r + b.y, 0.0f);
            a2  = fmaxf(a2  + b.z, 0.0f);
            a3  = fmaxf(a3  + b.w, 0.0f);
        }

        // layer-2 GEMM: lane owns output cols 2*lane, 2*lane+1
        float h0 = 0.0f, h1v = 0.0f;
        int c0 = lane * 2;
#pragma unroll
        for (int kk = 0; kk < 32; kk++) {
            float v0 = __shfl_sync(0xffffffffu, a0,  kk);
            float v1 = __shfl_sync(0xffffffffu, a1r, kk);
            float v2 = __shfl_sync(0xffffffffu, a2,  kk);
            float v3 = __shfl_sync(0xffffffffu, a3,  kk);
            const float* wr = &Wsm[(kk * 4) * OUT_C + c0];
            float2 w0 = *(const float2*)(wr);
            float2 w1 = *(const float2*)(wr + OUT_C);
            float2 w2 = *(const float2*)(wr + 2 * OUT_C);
            float2 w3 = *(const float2*)(wr + 3 * OUT_C);
            h0  += v0 * w0.x + v1 * w1.x + v2 * w2.x + v3 * w3.x;
            h1v += v0 * w0.y + v1 * w1.y + v2 * w2.y + v3 * w3.y;
        }
        *(float2*)(g_h2 + (size_t)node * OUT_C + c0) = make_float2(h0, h1v);
    }
}

// ---------------- CSR gather aggregation (layer 2): warp per dst node --------
__global__ void gather2_kernel(int n) {
    constexpr int FEAT = OUT_C;
    int t = blockIdx.x * blockDim.x + threadIdx.x;
    int node = t >> 5;
    int lane = t & 31;
    if (node >= n) return;

    float di = g_dinv[node];
    float sc = di * di;

    float acc0, acc1;
    {
        float2 f = *(const float2*)(g_h2 + (size_t)node * FEAT + lane * 2);
        acc0 = f.x * sc; acc1 = f.y * sc;
    }

    int i   = g_off[node];
    int end = g_off[node + 1];

    for (; i + 4 <= end; i += 4) {
        int2 c0 = g_csr[i];
        int2 c1 = g_csr[i + 1];
        int2 c2 = g_csr[i + 2];
        int2 c3 = g_csr[i + 3];
        const float* p0 = g_h2 + (size_t)c0.x * FEAT + lane * 2;
        const float* p1 = g_h2 + (size_t)c1.x * FEAT + lane * 2;
        const float* p2 = g_h2 + (size_t)c2.x * FEAT + lane * 2;
        const float* p3 = g_h2 + (size_t)c3.x * FEAT + lane * 2;
        float w0 = __int_as_float(c0.y), w1 = __int_as_float(c1.y);
        float w2 = __int_as_float(c2.y), w3 = __int_as_float(c3.y);
        float2 v0 = *(const float2*)p0;
        float2 v1 = *(const float2*)p1;
        float2 v2 = *(const float2*)p2;
        float2 v3 = *(const float2*)p3;
        acc0 += v0.x * w0 + v1.x * w1 + v2.x * w2 + v3.x * w3;
        acc1 += v0.y * w0 + v1.y * w1 + v2.y * w2 + v3.y * w3;
    }
    for (; i < end; i++) {
        int2 c = g_csr[i];
        float w = __int_as_float(c.y);
        float2 v = *(const float2*)(g_h2 + (size_t)c.x * FEAT + lane * 2);
        acc0 += v.x * w; acc1 += v.y * w;
    }

    *(float2*)(g_z + (size_t)node * FEAT + lane * 2) = make_float2(acc0, acc1);
}

// ---------------- decode: out[e] = dot(z[a]+b2, z[b]+b2) over 64 dims --------
__global__ void decode_kernel(const int* __restrict__ ea,
                              const int* __restrict__ eb,
                              const float* __restrict__ b2,
                              float* __restrict__ out, int ne) {
    long long t = (long long)blockIdx.x * blockDim.x + threadIdx.x;
    int e = (int)(t >> 5);
    int lane = (int)(t & 31);
    if (e >= ne) return;
    int a = ea[e];
    int b = eb[e];
    float2 bb = *(const float2*)(b2 + lane * 2);
    float2 va = *(const float2*)(g_z + (size_t)a * 64 + lane * 2);
    float2 vb = *(const float2*)(g_z + (size_t)b * 64 + lane * 2);
    va.x += bb.x; va.y += bb.y;
    vb.x += bb.x; vb.y += bb.y;
    float p = va.x * vb.x + va.y * vb.y;
#pragma unroll
    for (int o = 16; o > 0; o >>= 1) p += __shfl_down_sync(0xffffffffu, p, o);
    if (lane == 0) out[e] = p;
}

// ---------------- host launch ------------------------------------------------
static inline int cdiv_ll(long long a, int b) { return (int)((a + b - 1) / b); }

extern "C" void kernel_launch(void* const* d_in, const int* in_sizes, int n_in,
                              void* d_out, int out_size) {
    const float* x   = (const float*)d_in[0];
    const int*   ei  = (const int*)d_in[1];    // [2, E] int32
    const float* ew  = (const float*)d_in[2];
    const int*   eli = (const int*)d_in[3];    // [2, EL] int32
    const float* W1  = (const float*)d_in[4];
    const float* b1  = (const float*)d_in[5];
    const float* W2  = (const float*)d_in[6];
    const float* b2  = (const float*)d_in[7];
    float*       out = (float*)d_out;

    const int N  = in_sizes[0] / IN_C;
    const int E  = in_sizes[1] / 2;
    const int EL = in_sizes[3] / 2;

    const int* src = ei;
    const int* dst = ei + E;
    const int* ea  = eli;
    const int* eb  = eli + EL;

    const int T = 256;
    const int nb = (N + SCAN_BT - 1) / SCAN_BT;

    static cudaStream_t s2 = nullptr;
    static cudaEvent_t evA = nullptr, evB = nullptr, evC = nullptr;
    if (s2 == nullptr) {
        cudaStreamCreateWithFlags(&s2, cudaStreamNonBlocking);
        cudaEventCreateWithFlags(&evA, cudaEventDisableTiming);
        cudaEventCreateWithFlags(&evB, cudaEventDisableTiming);
        cudaEventCreateWithFlags(&evC, cudaEventDisableTiming);
    }

    // fork: gemm1 (independent of graph structure) runs on s2
    cudaEventRecord(evA, 0);
    cudaStreamWaitEvent(s2, evA, 0);
    gemm1_kernel<<<cdiv_ll(N, 64), 256, 0, s2>>>(x, W1, N);
    cudaEventRecord(evB, s2);

    // CSR build + normalization on the main (capture) stream
    deg_cnt_kernel<<<cdiv_ll(E, T), T>>>(dst, ew, E);
    scanA_kernel<<<nb, SCAN_BT>>>(N);
    scanB_kernel<<<nb, SCAN_BT>>>(N, nb);
    fill_kernel<<<cdiv_ll(E, T), T>>>(src, dst, ew, E);

    // cleanup (deg/cnt dead after scanB) — off the critical path on s2
    cudaStreamWaitEvent(s2, evA, 0);
    cleanup_kernel<<<cdiv_ll(N, T), T, 0, s2>>>(N);
    cudaEventRecord(evC, s2);

    // join: fused gather1+gemm2 needs h1 (s2) and CSR (main)
    cudaStreamWaitEvent(0, evB, 0);
    gather_gemm_kernel<<<FG_BLOCKS, 256>>>(W2, b1, N);

    // layer 2 aggregation + decode on main stream
    gather2_kernel<<<cdiv_ll((long long)N * 32, T), T>>>(N);
    decode_kernel<<<cdiv_ll((long long)EL * 32, T), T>>>(ea, eb, b2, out, EL);

    // graph end state includes cleanup
    cudaStreamWaitEvent(0, evC, 0);
}

// round 15
// speedup vs baseline: 1.2303x; 1.2303x over previous
#include <cuda_runtime.h>
#include <cuda_bf16.h>
#include <stdint.h>

// ---------------- problem constants (shapes fixed by the dataset) -----------
#define MAXN 100000
#define MAXE 1600000
#define IN_C 128
#define HID_C 128
#define OUT_C 64
#define SCAN_BT 1024

// ---------------- device scratch (no allocs; referenced directly) -----------
// g_deg / g_cnt are zero at module load; cleanup_kernel restores them to zero
// every call (off the critical path), keeping kernel_launch deterministic.
__device__ __align__(16) float g_deg [MAXN];
__device__ __align__(16) float g_dinv[MAXN];
__device__ __align__(16) int   g_cnt [MAXN];
__device__ __align__(16) int   g_cur [MAXN];
__device__ __align__(16) int   g_off [MAXN + 1];
__device__ __align__(16) int   g_bsum[128];
__device__ __align__(16) int2  g_csr [MAXE + 2];      // (src, w-as-bits); +2 pad for int4 tail
__device__ __align__(16) float g_h1[(size_t)MAXN * HID_C];
__device__ __align__(16) float g_a1[(size_t)MAXN * HID_C];
__device__ __align__(16) float g_h2[(size_t)MAXN * OUT_C];
__device__ __align__(16) float g_z [(size_t)MAXN * OUT_C];

// ---------------- degree + in-edge counting (arrays pre-zeroed) -------------
__global__ void deg_cnt_kernel(const int* __restrict__ dst,
                               const float* __restrict__ ew, int ne) {
    int e = blockIdx.x * blockDim.x + threadIdx.x;
    if (e < ne) {
        int d = dst[e];
        atomicAdd(&g_deg[d], ew[e]);
        atomicAdd(&g_cnt[d], 1);
    }
}

// ---------------- scan pass A: dinv + per-block sums of cnt -----------------
__global__ void scanA_kernel(int n) {
    __shared__ int wsum[32];
    int tid = threadIdx.x;
    int i = blockIdx.x * SCAN_BT + tid;
    int v = 0;
    if (i < n) {
        v = g_cnt[i];
        g_dinv[i] = rsqrtf(g_deg[i] + 1.0f);   // +1 = self-loop weight
    }
    int s = v;
#pragma unroll
    for (int o = 16; o > 0; o >>= 1) s += __shfl_down_sync(0xffffffffu, s, o);
    if ((tid & 31) == 0) wsum[tid >> 5] = s;
    __syncthreads();
    if (tid < 32) {
        int t = wsum[tid];
#pragma unroll
        for (int o = 16; o > 0; o >>= 1) t += __shfl_down_sync(0xffffffffu, t, o);
        if (tid == 0) g_bsum[blockIdx.x] = t;
    }
}

// ---------------- scan pass B: full exclusive scan -> g_off, g_cur ----------
__global__ void scanB_kernel(int n, int nb) {
    __shared__ int bsh[128];
    __shared__ int wpre[32];
    int tid = threadIdx.x;
    int lane = tid & 31;
    int wid = tid >> 5;

    if (tid < 128) bsh[tid] = (tid < nb) ? g_bsum[tid] : 0;
    __syncthreads();
#pragma unroll
    for (int o = 1; o < 128; o <<= 1) {
        int y = 0;
        if (tid >= o && tid < 128) y = bsh[tid - o];
        __syncthreads();
        if (tid >= o && tid < 128) bsh[tid] += y;
        __syncthreads();
    }
    int bpre = bsh[blockIdx.x] - g_bsum[blockIdx.x];   // exclusive block prefix

    int i = blockIdx.x * SCAN_BT + tid;
    int v = (i < n) ? g_cnt[i] : 0;
    int x = v;
#pragma unroll
    for (int o = 1; o < 32; o <<= 1) {
        int y = __shfl_up_sync(0xffffffffu, x, o);
        if (lane >= o) x += y;
    }
    if (lane == 31) wpre[wid] = x;
    __syncthreads();
    if (wid == 0) {
        int t = wpre[lane];
        int tv = t;
#pragma unroll
        for (int o = 1; o < 32; o <<= 1) {
            int y = __shfl_up_sync(0xffffffffu, tv, o);
            if (lane >= o) tv += y;
        }
        wpre[lane] = tv - t;
    }
    __syncthreads();
    int excl = bpre + wpre[wid] + (x - v);
    if (i < n) {
        g_off[i] = excl;
        g_cur[i] = excl;
        if (i == n - 1) g_off[n] = excl + v;
    }
}

// fill CSR: (src, w) pairs grouped by dst
__global__ void fill_kernel(const int* __restrict__ src,
                            const int* __restrict__ dst,
                            const float* __restrict__ ew, int ne) {
    int e = blockIdx.x * blockDim.x + threadIdx.x;
    if (e >= ne) return;
    int s = src[e];
    int d = dst[e];
    int slot = atomicAdd(&g_cur[d], 1);
    float w = g_dinv[s] * ew[e] * g_dinv[d];
    g_csr[slot] = make_int2(s, __float_as_int(w));
}

// restore scratch counters to zero for the next call (determinism)
__global__ void cleanup_kernel(int n) {
    int i = blockIdx.x * blockDim.x + threadIdx.x;
    if (i < n) { g_deg[i] = 0.0f; g_cnt[i] = 0; }
}

// ---------------- tiled FP32 GEMM -------------------------------------------
// LAYER 1: A = X (arg),         C = g_h1
// LAYER 2: A = relu(g_a1 + b1), C = g_h2
template<int NOUT, int LAYER>
__global__ void gemm_kernel(const float* __restrict__ X,
                            const float* __restrict__ W,
                            const float* __restrict__ bias_in,
                            int nrows) {
    const float* __restrict__ A = (LAYER == 1) ? X : (const float*)g_a1;
    float* __restrict__ C = (LAYER == 1) ? g_h1 : g_h2;

    constexpr int CPT = NOUT / 16;
    __shared__ float As[64][33];
    __shared__ float Ws[32 * NOUT];

    int tid = threadIdx.x;
    int tx = tid & 15, ty = tid >> 4;
    int row0 = blockIdx.x * 64;

    float acc[4][CPT];
#pragma unroll
    for (int i = 0; i < 4; i++)
#pragma unroll
        for (int j = 0; j < CPT; j++) acc[i][j] = 0.0f;

    for (int k0 = 0; k0 < 128; k0 += 32) {
#pragma unroll
        for (int i = 0; i < 2; i++) {
            int idx = tid + i * 256;
            int r  = idx >> 3;
            int cs = (idx & 7) * 4;
            float4 v = make_float4(0.f, 0.f, 0.f, 0.f);
            int row = row0 + r;
            if (row < nrows) {
                v = __ldg((const float4*)(A + (size_t)row * 128 + k0 + cs));
                if (LAYER == 2) {
                    float4 b = __ldg((const float4*)(bias_in + k0 + cs));
                    v.x = fmaxf(v.x + b.x, 0.0f);
                    v.y = fmaxf(v.y + b.y, 0.0f);
                    v.z = fmaxf(v.z + b.z, 0.0f);
                    v.w = fmaxf(v.w + b.w, 0.0f);
                }
            }
            As[r][cs + 0] = v.x; As[r][cs + 1] = v.y;
            As[r][cs + 2] = v.z; As[r][cs + 3] = v.w;
        }
        constexpr int WV = (32 * NOUT) / 4 / 256;
        const float4* Wg = (const float4*)(W + k0 * NOUT);
        float4* Wsv = (float4*)Ws;
#pragma unroll
        for (int i = 0; i < WV; i++) Wsv[tid + i * 256] = __ldg(Wg + tid + i * 256);
        __syncthreads();

#pragma unroll
        for (int k = 0; k < 32; k++) {
            float a0 = As[ty * 4 + 0][k];
            float a1v = As[ty * 4 + 1][k];
            float a2 = As[ty * 4 + 2][k];
            float a3 = As[ty * 4 + 3][k];
            const float* wrow = &Ws[k * NOUT + tx * CPT];
#pragma unroll
            for (int j = 0; j < CPT; j++) {
                float b = wrow[j];
                acc[0][j] += a0 * b;
                acc[1][j] += a1v * b;
                acc[2][j] += a2 * b;
                acc[3][j] += a3 * b;
            }
        }
        __syncthreads();
    }

#pragma unroll
    for (int i = 0; i < 4; i++) {
        int row = row0 + ty * 4 + i;
        if (row < nrows) {
            float* cp = C + (size_t)row * NOUT + tx * CPT;
#pragma unroll
            for (int j = 0; j < CPT; j += 4)
                *(float4*)(cp + j) = make_float4(acc[i][j], acc[i][j + 1],
                                                 acc[i][j + 2], acc[i][j + 3]);
        }
    }
}

// ---------------- CSR gather aggregation: warp per dst node ------------------
// Out[n] = H[n]*dinv[n]^2 + sum_{in-edges e} w_e * H[src_e]
// CSR consumed as int4 pairs (2 edges per load) when 16B-aligned.
template<int FEAT, int LAYER>
__global__ void gather_kernel(int n) {
    const float* __restrict__ H = (LAYER == 1) ? g_h1 : g_h2;
    float* __restrict__ Out = (LAYER == 1) ? g_a1 : g_z;
    constexpr int VW = FEAT / 32;            // floats per lane (4 or 2)

    int t = blockIdx.x * blockDim.x + threadIdx.x;
    int node = t >> 5;
    int lane = t & 31;
    if (node >= n) return;

    float di = g_dinv[node];
    float sc = di * di;

    float acc[VW];
    {
        const float* hp = H + (size_t)node * FEAT + lane * VW;
        if constexpr (VW == 4) {
            float4 f = *(const float4*)hp;
            acc[0] = f.x * sc; acc[1] = f.y * sc; acc[2] = f.z * sc; acc[3] = f.w * sc;
        } else {
            float2 f = *(const float2*)hp;
            acc[0] = f.x * sc; acc[1] = f.y * sc;
        }
    }

    int i   = g_off[node];
    int end = g_off[node + 1];

    // align to int4 boundary (g_csr is 16B-aligned; pair index even => aligned)
    if ((i & 1) && i < end) {
        int2 c = g_csr[i++];
        float w = __int_as_float(c.y);
        const float* p = H + (size_t)c.x * FEAT + lane * VW;
        if constexpr (VW == 4) {
            float4 v = *(const float4*)p;
            acc[0] += v.x * w; acc[1] += v.y * w;
            acc[2] += v.z * w; acc[3] += v.w * w;
        } else {
            float2 v = *(const float2*)p;
            acc[0] += v.x * w; acc[1] += v.y * w;
        }
    }

    for (; i + 4 <= end; i += 4) {
        int4 cc0 = *(const int4*)&g_csr[i];        // edges i, i+1
        int4 cc1 = *(const int4*)&g_csr[i + 2];    // edges i+2, i+3
        const float* p0 = H + (size_t)cc0.x * FEAT + lane * VW;
        const float* p1 = H + (size_t)cc0.z * FEAT + lane * VW;
        const float* p2 = H + (size_t)cc1.x * FEAT + lane * VW;
        const float* p3 = H + (size_t)cc1.z * FEAT + lane * VW;
        float w0 = __int_as_float(cc0.y), w1 = __int_as_float(cc0.w);
        float w2 = __int_as_float(cc1.y), w3 = __int_as_float(cc1.w);
        if constexpr (VW == 4) {
            float4 v0 = *(const float4*)p0;
            float4 v1 = *(const float4*)p1;
            float4 v2 = *(const float4*)p2;
            float4 v3 = *(const float4*)p3;
            acc[0] += v0.x * w0 + v1.x * w1 + v2.x * w2 + v3.x * w3;
            acc[1] += v0.y * w0 + v1.y * w1 + v2.y * w2 + v3.y * w3;
            acc[2] += v0.z * w0 + v1.z * w1 + v2.z * w2 + v3.z * w3;
            acc[3] += v0.w * w0 + v1.w * w1 + v2.w * w2 + v3.w * w3;
        } else {
            float2 v0 = *(const float2*)p0;
            float2 v1 = *(const float2*)p1;
            float2 v2 = *(const float2*)p2;
            float2 v3 = *(const float2*)p3;
            acc[0] += v0.x * w0 + v1.x * w1 + v2.x * w2 + v3.x * w3;
            acc[1] += v0.y * w0 + v1.y * w1 + v2.y * w2 + v3.y * w3;
        }
    }
    for (; i < end; i++) {
        int2 c = g_csr[i];
        float w = __int_as_float(c.y);
        const float* p = H + (size_t)c.x * FEAT + lane * VW;
        if constexpr (VW == 4) {
            float4 v = *(const float4*)p;
            acc[0] += v.x * w; acc[1] += v.y * w;
            acc[2] += v.z * w; acc[3] += v.w * w;
        } else {
            float2 v = *(const float2*)p;
            acc[0] += v.x * w; acc[1] += v.y * w;
        }
    }

    float* op = Out + (size_t)node * FEAT + lane * VW;
    if constexpr (VW == 4)
        *(float4*)op = make_float4(acc[0], acc[1], acc[2], acc[3]);
    else
        *(float2*)op = make_float2(acc[0], acc[1]);
}

// ---------------- decode: out[e] = dot(z[a]+b2, z[b]+b2) over 64 dims --------
__global__ void decode_kernel(const int* __restrict__ ea,
                              const int* __restrict__ eb,
                              const float* __restrict__ b2,
                              float* __restrict__ out, int ne) {
    long long t = (long long)blockIdx.x * blockDim.x + threadIdx.x;
    int e = (int)(t >> 5);
    int lane = (int)(t & 31);
    if (e >= ne) return;
    int a = ea[e];
    int b = eb[e];
    float2 bb = *(const float2*)(b2 + lane * 2);
    float2 va = *(const float2*)(g_z + (size_t)a * 64 + lane * 2);
    float2 vb = *(const float2*)(g_z + (size_t)b * 64 + lane * 2);
    va.x += bb.x; va.y += bb.y;
    vb.x += bb.x; vb.y += bb.y;
    float p = va.x * vb.x + va.y * vb.y;
#pragma unroll
    for (int o = 16; o > 0; o >>= 1) p += __shfl_down_sync(0xffffffffu, p, o);
    if (lane == 0) out[e] = p;
}

// ---------------- host launch ------------------------------------------------
static inline int cdiv_ll(long long a, int b) { return (int)((a + b - 1) / b); }

extern "C" void kernel_launch(void* const* d_in, const int* in_sizes, int n_in,
                              void* d_out, int out_size) {
    const float* x   = (const float*)d_in[0];
    const int*   ei  = (const int*)d_in[1];    // [2, E] int32
    const float* ew  = (const float*)d_in[2];
    const int*   eli = (const int*)d_in[3];    // [2, EL] int32
    const float* W1  = (const float*)d_in[4];
    const float* b1  = (const float*)d_in[5];
    const float* W2  = (const float*)d_in[6];
    const float* b2  = (const float*)d_in[7];
    float*       out = (float*)d_out;

    const int N  = in_sizes[0] / IN_C;
    const int E  = in_sizes[1] / 2;
    const int EL = in_sizes[3] / 2;

    const int* src = ei;
    const int* dst = ei + E;
    const int* ea  = eli;
    const int* eb  = eli + EL;

    const int T = 256;
    const int nb = (N + SCAN_BT - 1) / SCAN_BT;

    static cudaStream_t s2 = nullptr;
    static cudaEvent_t evA = nullptr, evB = nullptr, evC = nullptr;
    if (s2 == nullptr) {
        cudaStreamCreateWithFlags(&s2, cudaStreamNonBlocking);
        cudaEventCreateWithFlags(&evA, cudaEventDisableTiming);
        cudaEventCreateWithFlags(&evB, cudaEventDisableTiming);
        cudaEventCreateWithFlags(&evC, cudaEventDisableTiming);
    }

    // fork: gemm1 (independent of graph structure) runs on s2
    cudaEventRecord(evA, 0);
    cudaStreamWaitEvent(s2, evA, 0);
    gemm_kernel<HID_C, 1><<<cdiv_ll(N, 64), 256, 0, s2>>>(x, W1, nullptr, N);
    cudaEventRecord(evB, s2);

    // CSR build + normalization on the main (capture) stream
    deg_cnt_kernel<<<cdiv_ll(E, T), T>>>(dst, ew, E);
    scanA_kernel<<<nb, SCAN_BT>>>(N);
    scanB_kernel<<<nb, SCAN_BT>>>(N, nb);
    fill_kernel<<<cdiv_ll(E, T), T>>>(src, dst, ew, E);

    // cleanup (deg/cnt dead after scanB) — off the critical path on s2
    cudaStreamWaitEvent(s2, evA, 0);
    cleanup_kernel<<<cdiv_ll(N, T), T, 0, s2>>>(N);
    cudaEventRecord(evC, s2);

    // join: gather1 needs both h1 (s2) and CSR (main)
    cudaStreamWaitEvent(0, evB, 0);
    gather_kernel<HID_C, 1><<<cdiv_ll((long long)N * 32, T), T>>>(N);

    // layer 2 + decode on main stream
    gemm_kernel<OUT_C, 2><<<cdiv_ll(N, 64), 256>>>(x, W2, b1, N);
    gather_kernel<OUT_C, 2><<<cdiv_ll((long long)N * 32, T), T>>>(N);
    decode_kernel<<<cdiv_ll((long long)EL * 32, T), T>>>(ea, eb, b2, out, EL);

    // graph end state includes cleanup
    cudaStreamWaitEvent(0, evC, 0);
}

// round 16
// speedup vs baseline: 1.3013x; 1.0577x over previous
#include <cuda_runtime.h>
#include <cuda_bf16.h>
#include <stdint.h>

// ---------------- problem constants (shapes fixed by the dataset) -----------
#define MAXN 100000
#define MAXE 1600000
#define IN_C 128
#define HID_C 128
#define OUT_C 64
#define SCAN_BT 1024

// ---------------- device scratch (no allocs; referenced directly) -----------
// g_deg / g_cnt are zero at module load; cleanup_kernel restores them to zero
// every call (off the critical path), keeping kernel_launch deterministic.
__device__ __align__(16) float g_deg [MAXN];
__device__ __align__(16) float g_dinv[MAXN];
__device__ __align__(16) int   g_cnt [MAXN];
__device__ __align__(16) int   g_cur [MAXN];
__device__ __align__(16) int   g_off [MAXN + 1];
__device__ __align__(16) int   g_bsum[128];
__device__ __align__(16) int2  g_csr [MAXE];          // (src, w-as-bits)
__device__ __align__(16) float g_h1[(size_t)MAXN * HID_C];
__device__ __align__(16) float g_a1[(size_t)MAXN * HID_C];
__device__ __align__(16) float g_h2[(size_t)MAXN * OUT_C];
__device__ __align__(16) float g_z [(size_t)MAXN * OUT_C];

// ---------------- degree + in-edge counting (arrays pre-zeroed) -------------
__global__ void deg_cnt_kernel(const int* __restrict__ dst,
                               const float* __restrict__ ew, int ne) {
    int e = blockIdx.x * blockDim.x + threadIdx.x;
    if (e < ne) {
        int d = dst[e];
        atomicAdd(&g_deg[d], ew[e]);
        atomicAdd(&g_cnt[d], 1);
    }
}

// ---------------- scan pass A: dinv + per-block sums of cnt -----------------
__global__ void scanA_kernel(int n) {
    __shared__ int wsum[32];
    int tid = threadIdx.x;
    int i = blockIdx.x * SCAN_BT + tid;
    int v = 0;
    if (i < n) {
        v = g_cnt[i];
        g_dinv[i] = rsqrtf(g_deg[i] + 1.0f);   // +1 = self-loop weight
    }
    int s = v;
#pragma unroll
    for (int o = 16; o > 0; o >>= 1) s += __shfl_down_sync(0xffffffffu, s, o);
    if ((tid & 31) == 0) wsum[tid >> 5] = s;
    __syncthreads();
    if (tid < 32) {
        int t = wsum[tid];
#pragma unroll
        for (int o = 16; o > 0; o >>= 1) t += __shfl_down_sync(0xffffffffu, t, o);
        if (tid == 0) g_bsum[blockIdx.x] = t;
    }
}

// ---------------- scan pass B: full exclusive scan -> g_off, g_cur ----------
__global__ void scanB_kernel(int n, int nb) {
    __shared__ int bsh[128];
    __shared__ int wpre[32];
    int tid = threadIdx.x;
    int lane = tid & 31;
    int wid = tid >> 5;

    if (tid < 128) bsh[tid] = (tid < nb) ? g_bsum[tid] : 0;
    __syncthreads();
#pragma unroll
    for (int o = 1; o < 128; o <<= 1) {
        int y = 0;
        if (tid >= o && tid < 128) y = bsh[tid - o];
        __syncthreads();
        if (tid >= o && tid < 128) bsh[tid] += y;
        __syncthreads();
    }
    int bpre = bsh[blockIdx.x] - g_bsum[blockIdx.x];   // exclusive block prefix

    int i = blockIdx.x * SCAN_BT + tid;
    int v = (i < n) ? g_cnt[i] : 0;
    int x = v;
#pragma unroll
    for (int o = 1; o < 32; o <<= 1) {
        int y = __shfl_up_sync(0xffffffffu, x, o);
        if (lane >= o) x += y;
    }
    if (lane == 31) wpre[wid] = x;
    __syncthreads();
    if (wid == 0) {
        int t = wpre[lane];
        int tv = t;
#pragma unroll
        for (int o = 1; o < 32; o <<= 1) {
            int y = __shfl_up_sync(0xffffffffu, tv, o);
            if (lane >= o) tv += y;
        }
        wpre[lane] = tv - t;
    }
    __syncthreads();
    int excl = bpre + wpre[wid] + (x - v);
    if (i < n) {
        g_off[i] = excl;
        g_cur[i] = excl;
        if (i == n - 1) g_off[n] = excl + v;
    }
}

// fill CSR: (src, w) pairs grouped by dst
__global__ void fill_kernel(const int* __restrict__ src,
                            const int* __restrict__ dst,
                            const float* __restrict__ ew, int ne) {
    int e = blockIdx.x * blockDim.x + threadIdx.x;
    if (e >= ne) return;
    int s = src[e];
    int d = dst[e];
    int slot = atomicAdd(&g_cur[d], 1);
    float w = g_dinv[s] * ew[e] * g_dinv[d];
    g_csr[slot] = make_int2(s, __float_as_int(w));
}

// restore scratch counters to zero for the next call (determinism)
__global__ void cleanup_kernel(int n) {
    int i = blockIdx.x * blockDim.x + threadIdx.x;
    if (i < n) { g_deg[i] = 0.0f; g_cnt[i] = 0; }
}

// ---------------- tiled FP32 GEMM, 8x8 register blocking ---------------------
// C[nrows, NOUT] = A[nrows,128] @ W[128,NOUT]
// Tile: 128 rows x NOUT cols, 256 threads, K-chunk 16, A staged transposed.
// LAYER 1: A = X (arg), C = g_h1.  LAYER 2: A = relu(g_a1+b1), C = g_h2.
template<int NOUT, int LAYER>
__global__ __launch_bounds__(256) void gemm_kernel(const float* __restrict__ X,
                                                   const float* __restrict__ W,
                                                   const float* __restrict__ bias_in,
                                                   int nrows) {
    const float* __restrict__ A = (LAYER == 1) ? X : (const float*)g_a1;
    float* __restrict__ C = (LAYER == 1) ? g_h1 : g_h2;

    constexpr int KC  = 16;
    constexpr int TX  = NOUT / 8;            // threads in col dir (16 or 8)
    constexpr int TY  = 256 / TX;            // threads in row dir (16 or 32)
    constexpr int RPT = 128 / TY;            // rows per thread (8 or 4)
    constexpr int APAD = 4;

    __shared__ float As[KC][128 + APAD];     // transposed: As[k][row]
    __shared__ float Bs[KC][NOUT];

    int tid = threadIdx.x;
    int tx = tid % TX, ty = tid / TX;
    int row0 = blockIdx.x * 128;
    int rbase = ty * RPT;
    int cbase = tx * 8;

    float acc[RPT][8];
#pragma unroll
    for (int i = 0; i < RPT; i++)
#pragma unroll
        for (int j = 0; j < 8; j++) acc[i][j] = 0.0f;

    for (int k0 = 0; k0 < 128; k0 += KC) {
        // A chunk: 128 rows x 16 k = 512 float4, 2 per thread; store transposed
#pragma unroll
        for (int i = 0; i < 2; i++) {
            int idx = tid + i * 256;         // 0..511
            int r  = idx >> 2;               // 0..127
            int kc = (idx & 3) * 4;          // 0,4,8,12
            float4 v = make_float4(0.f, 0.f, 0.f, 0.f);
            int row = row0 + r;
            if (row < nrows) {
                v = *(const float4*)(A + (size_t)row * 128 + k0 + kc);
                if (LAYER == 2) {
                    float4 b = *(const float4*)(bias_in + k0 + kc);
                    v.x = fmaxf(v.x + b.x, 0.0f);
                    v.y = fmaxf(v.y + b.y, 0.0f);
                    v.z = fmaxf(v.z + b.z, 0.0f);
                    v.w = fmaxf(v.w + b.w, 0.0f);
                }
            }
            As[kc + 0][r] = v.x; As[kc + 1][r] = v.y;
            As[kc + 2][r] = v.z; As[kc + 3][r] = v.w;
        }
        // B chunk: 16 rows x NOUT cols
        constexpr int BV = KC * NOUT / 4 / 256;   // float4/thread (2 or 1)
#pragma unroll
        for (int i = 0; i < BV; i++) {
            int idx = tid + i * 256;
            int r  = idx / (NOUT / 4);
            int c4 = (idx % (NOUT / 4)) * 4;
            *(float4*)&Bs[r][c4] = *(const float4*)(W + (size_t)(k0 + r) * NOUT + c4);
        }
        __syncthreads();

#pragma unroll
        for (int k = 0; k < KC; k++) {
            float a[RPT], b[8];
#pragma unroll
            for (int i = 0; i < RPT; i += 4)
                *(float4*)&a[i] = *(const float4*)&As[k][rbase + i];
            *(float4*)&b[0] = *(const float4*)&Bs[k][cbase];
            *(float4*)&b[4] = *(const float4*)&Bs[k][cbase + 4];
#pragma unroll
            for (int i = 0; i < RPT; i++)
#pragma unroll
                for (int j = 0; j < 8; j++)
                    acc[i][j] += a[i] * b[j];
        }
        __syncthreads();
    }

#pragma unroll
    for (int i = 0; i < RPT; i++) {
        int row = row0 + rbase + i;
        if (row < nrows) {
            float* cp = C + (size_t)row * NOUT + cbase;
            *(float4*)(cp)     = make_float4(acc[i][0], acc[i][1], acc[i][2], acc[i][3]);
            *(float4*)(cp + 4) = make_float4(acc[i][4], acc[i][5], acc[i][6], acc[i][7]);
        }
    }
}

// ---------------- CSR gather aggregation: warp per dst node ------------------
// Out[n] = H[n]*dinv[n]^2 + sum_{in-edges e} w_e * H[src_e]
template<int FEAT, int LAYER>
__global__ void gather_kernel(int n) {
    const float* __restrict__ H = (LAYER == 1) ? g_h1 : g_h2;
    float* __restrict__ Out = (LAYER == 1) ? g_a1 : g_z;
    constexpr int VW = FEAT / 32;            // floats per lane (4 or 2)

    int t = blockIdx.x * blockDim.x + threadIdx.x;
    int node = t >> 5;
    int lane = t & 31;
    if (node >= n) return;

    float di = g_dinv[node];
    float sc = di * di;

    float acc[VW];
    {
        const float* hp = H + (size_t)node * FEAT + lane * VW;
        if constexpr (VW == 4) {
            float4 f = *(const float4*)hp;
            acc[0] = f.x * sc; acc[1] = f.y * sc; acc[2] = f.z * sc; acc[3] = f.w * sc;
        } else {
            float2 f = *(const float2*)hp;
            acc[0] = f.x * sc; acc[1] = f.y * sc;
        }
    }

    int i   = g_off[node];
    int end = g_off[node + 1];

    for (; i + 4 <= end; i += 4) {
        int2 c0 = g_csr[i];
        int2 c1 = g_csr[i + 1];
        int2 c2 = g_csr[i + 2];
        int2 c3 = g_csr[i + 3];
        const float* p0 = H + (size_t)c0.x * FEAT + lane * VW;
        const float* p1 = H + (size_t)c1.x * FEAT + lane * VW;
        const float* p2 = H + (size_t)c2.x * FEAT + lane * VW;
        const float* p3 = H + (size_t)c3.x * FEAT + lane * VW;
        float w0 = __int_as_float(c0.y), w1 = __int_as_float(c1.y);
        float w2 = __int_as_float(c2.y), w3 = __int_as_float(c3.y);
        if constexpr (VW == 4) {
            float4 v0 = *(const float4*)p0;
            float4 v1 = *(const float4*)p1;
            float4 v2 = *(const float4*)p2;
            float4 v3 = *(const float4*)p3;
            acc[0] += v0.x * w0 + v1.x * w1 + v2.x * w2 + v3.x * w3;
            acc[1] += v0.y * w0 + v1.y * w1 + v2.y * w2 + v3.y * w3;
            acc[2] += v0.z * w0 + v1.z * w1 + v2.z * w2 + v3.z * w3;
            acc[3] += v0.w * w0 + v1.w * w1 + v2.w * w2 + v3.w * w3;
        } else {
            float2 v0 = *(const float2*)p0;
            float2 v1 = *(const float2*)p1;
            float2 v2 = *(const float2*)p2;
            float2 v3 = *(const float2*)p3;
            acc[0] += v0.x * w0 + v1.x * w1 + v2.x * w2 + v3.x * w3;
            acc[1] += v0.y * w0 + v1.y * w1 + v2.y * w2 + v3.y * w3;
        }
    }
    for (; i < end; i++) {
        int2 c = g_csr[i];
        float w = __int_as_float(c.y);
        const float* p = H + (size_t)c.x * FEAT + lane * VW;
        if constexpr (VW == 4) {
            float4 v = *(const float4*)p;
            acc[0] += v.x * w; acc[1] += v.y * w;
            acc[2] += v.z * w; acc[3] += v.w * w;
        } else {
            float2 v = *(const float2*)p;
            acc[0] += v.x * w; acc[1] += v.y * w;
        }
    }

    float* op = Out + (size_t)node * FEAT + lane * VW;
    if constexpr (VW == 4)
        *(float4*)op = make_float4(acc[0], acc[1], acc[2], acc[3]);
    else
        *(float2*)op = make_float2(acc[0], acc[1]);
}

// ---------------- decode: out[e] = dot(z[a]+b2, z[b]+b2) over 64 dims --------
__global__ void decode_kernel(const int* __restrict__ ea,
                              const int* __restrict__ eb,
                              const float* __restrict__ b2,
                              float* __restrict__ out, int ne) {
    long long t = (long long)blockIdx.x * blockDim.x + threadIdx.x;
    int e = (int)(t >> 5);
    int lane = (int)(t & 31);
    if (e >= ne) return;
    int a = ea[e];
    int b = eb[e];
    float2 bb = *(const float2*)(b2 + lane * 2);
    float2 va = *(const float2*)(g_z + (size_t)a * 64 + lane * 2);
    float2 vb = *(const float2*)(g_z + (size_t)b * 64 + lane * 2);
    va.x += bb.x; va.y += bb.y;
    vb.x += bb.x; vb.y += bb.y;
    float p = va.x * vb.x + va.y * vb.y;
#pragma unroll
    for (int o = 16; o > 0; o >>= 1) p += __shfl_down_sync(0xffffffffu, p, o);
    if (lane == 0) out[e] = p;
}

// ---------------- host launch ------------------------------------------------
static inline int cdiv_ll(long long a, int b) { return (int)((a + b - 1) / b); }

extern "C" void kernel_launch(void* const* d_in, const int* in_sizes, int n_in,
                              void* d_out, int out_size) {
    const float* x   = (const float*)d_in[0];
    const int*   ei  = (const int*)d_in[1];    // [2, E] int32
    const float* ew  = (const float*)d_in[2];
    const int*   eli = (const int*)d_in[3];    // [2, EL] int32
    const float* W1  = (const float*)d_in[4];
    const float* b1  = (const float*)d_in[5];
    const float* W2  = (const float*)d_in[6];
    const float* b2  = (const float*)d_in[7];
    float*       out = (float*)d_out;

    const int N  = in_sizes[0] / IN_C;
    const int E  = in_sizes[1] / 2;
    const int EL = in_sizes[3] / 2;

    const int* src = ei;
    const int* dst = ei + E;
    const int* ea  = eli;
    const int* eb  = eli + EL;

    const int T = 256;
    const int nb = (N + SCAN_BT - 1) / SCAN_BT;

    static cudaStream_t s2 = nullptr;
    static cudaEvent_t evA = nullptr, evB = nullptr, evC = nullptr;
    if (s2 == nullptr) {
        cudaStreamCreateWithFlags(&s2, cudaStreamNonBlocking);
        cudaEventCreateWithFlags(&evA, cudaEventDisableTiming);
        cudaEventCreateWithFlags(&evB, cudaEventDisableTiming);
        cudaEventCreateWithFlags(&evC, cudaEventDisableTiming);
    }

    // fork: gemm1 (independent of graph structure) runs on s2
    cudaEventRecord(evA, 0);
    cudaStreamWaitEvent(s2, evA, 0);
    gemm_kernel<HID_C, 1><<<cdiv_ll(N, 128), 256, 0, s2>>>(x, W1, nullptr, N);
    cudaEventRecord(evB, s2);

    // CSR build + normalization on the main (capture) stream
    deg_cnt_kernel<<<cdiv_ll(E, T), T>>>(dst, ew, E);
    scanA_kernel<<<nb, SCAN_BT>>>(N);
    scanB_kernel<<<nb, SCAN_BT>>>(N, nb);
    fill_kernel<<<cdiv_ll(E, T), T>>>(src, dst, ew, E);

    // cleanup (deg/cnt dead after scanB) — off the critical path on s2
    cudaStreamWaitEvent(s2, evA, 0);
    cleanup_kernel<<<cdiv_ll(N, T), T, 0, s2>>>(N);
    cudaEventRecord(evC, s2);

    // join: gather1 needs both h1 (s2) and CSR (main)
    cudaStreamWaitEvent(0, evB, 0);
    gather_kernel<HID_C, 1><<<cdiv_ll((long long)N * 32, T), T>>>(N);

    // layer 2 + decode on main stream
    gemm_kernel<OUT_C, 2><<<cdiv_ll(N, 128), 256>>>(x, W2, b1, N);
    gather_kernel<OUT_C, 2><<<cdiv_ll((long long)N * 32, T), T>>>(N);
    decode_kernel<<<cdiv_ll((long long)EL * 32, T), T>>>(ea, eb, b2, out, EL);

    // graph end state includes cleanup
    cudaStreamWaitEvent(0, evC, 0);
}